// round 10
// baseline (speedup 1.0000x reference)
#include <cuda_runtime.h>

// Problem constants
#define NN 100000
#define NE 1600000
constexpr float BN_EPS = 1e-5f;

constexpr int SCAN_TILE = 1024;
constexpr int NSCAN = (NN + SCAN_TILE - 1) / SCAN_TILE;   // 98
constexpr int NT_GEMM = (NN + 63) / 64;                   // 1563 row tiles

#define AGG_FLAG (1 << 30)
#define INC_FLAG (2 << 30)
#define VAL_MASK ((1 << 30) - 1)

// ---------------- scratch (static device globals; zero-initialized) -------
__device__ int   g_degcnt[NN];        // re-zeroed by k_scatter each replay
__device__ int   g_scanstate[NSCAN];  // re-zeroed by k_scatter each replay
__device__ float g_dis[NN];
__device__ int   g_rowptr[NN + 1];
__device__ int   g_fill[NN];
__device__ __align__(16) int2  g_cedge[NE];    // {src, float_bits(w)}
__device__ __align__(16) float g_ha[NN * 64];  // gemm outputs
__device__ __align__(16) float g_hb[NN * 64];  // agg outputs (layers 1,2)
__device__ float g_bn1[128];          // re-zeroed by k_agg40 each replay
__device__ float g_bn2[128];

// ---------------- degree count (int4-vectorized over dst half) ------------
__global__ void k_count(const int* __restrict__ ei) {
    const int4* d4 = reinterpret_cast<const int4*>(ei + NE);
    int i = blockIdx.x * blockDim.x + threadIdx.x;
    int stride = gridDim.x * blockDim.x;
    for (int e = i; e < NE / 4; e += stride) {
        int4 d = __ldg(&d4[e]);
        atomicAdd(&g_degcnt[d.x], 1);
        atomicAdd(&g_degcnt[d.y], 1);
        atomicAdd(&g_degcnt[d.z], 1);
        atomicAdd(&g_degcnt[d.w], 1);
    }
}

// ---------------- single-kernel decoupled-lookback scan --------------------
// Also writes rowptr/fill/dis (old scanC). All 98 blocks resident at once.
__global__ void k_scan() {
    __shared__ int sm[SCAN_TILE];
    __shared__ int s_prefix;
    const int t = threadIdx.x;
    const int b = blockIdx.x;
    const int i = b * SCAN_TILE + t;

    int v = (i < NN) ? g_degcnt[i] : 0;
    sm[t] = v;
    __syncthreads();
    #pragma unroll
    for (int off = 1; off < SCAN_TILE; off <<= 1) {
        int add = (t >= off) ? sm[t - off] : 0;
        __syncthreads();
        sm[t] += add;
        __syncthreads();
    }
    int incl = sm[t];
    int agg  = sm[SCAN_TILE - 1];

    if (t == 0) {
        if (b == 0) {
            atomicExch(&g_scanstate[0], INC_FLAG | agg);
            s_prefix = 0;
        } else {
            atomicExch(&g_scanstate[b], AGG_FLAG | agg);
            int run = 0;
            int idx = b - 1;
            while (true) {
                int st = atomicAdd(&g_scanstate[idx], 0);
                if (st == 0) continue;          // not yet published
                run += st & VAL_MASK;
                if (st & INC_FLAG) break;
                idx--;
            }
            atomicExch(&g_scanstate[b], INC_FLAG | (run + agg));
            s_prefix = run;
        }
    }
    __syncthreads();

    int excl = s_prefix + incl - v;
    if (i < NN) {
        g_rowptr[i] = excl;
        g_fill[i]   = excl;
        g_dis[i]    = rsqrtf((float)(v + 1));
    }
    if (i == 0) g_rowptr[NN] = NE;
}

// ---------------- CSR scatter (int4 loads) + state resets ------------------
__global__ void k_scatter(const int* __restrict__ ei) {
    const int4* s4 = reinterpret_cast<const int4*>(ei);
    const int4* d4 = reinterpret_cast<const int4*>(ei + NE);
    int i = blockIdx.x * blockDim.x + threadIdx.x;
    int stride = gridDim.x * blockDim.x;
    for (int e = i; e < NE / 4; e += stride) {
        int4 s = __ldg(&s4[e]);
        int4 d = __ldg(&d4[e]);
        {
            float w = g_dis[s.x] * g_dis[d.x];
            g_cedge[atomicAdd(&g_fill[d.x], 1)] = make_int2(s.x, __float_as_int(w));
        }
        {
            float w = g_dis[s.y] * g_dis[d.y];
            g_cedge[atomicAdd(&g_fill[d.y], 1)] = make_int2(s.y, __float_as_int(w));
        }
        {
            float w = g_dis[s.z] * g_dis[d.z];
            g_cedge[atomicAdd(&g_fill[d.z], 1)] = make_int2(s.z, __float_as_int(w));
        }
        {
            float w = g_dis[s.w] * g_dis[d.w];
            g_cedge[atomicAdd(&g_fill[d.w], 1)] = make_int2(s.w, __float_as_int(w));
        }
    }
    // reset per-replay state (consumed already this replay)
    for (int n = i; n < NN; n += stride) g_degcnt[n] = 0;
    if (i < NSCAN) g_scanstate[i] = 0;
}

// ---------------- f32x2 helper ---------------------------------------------
__device__ __forceinline__ void ffma2(unsigned long long& d,
                                      unsigned long long a,
                                      unsigned long long b) {
    asm("fma.rn.f32x2 %0, %1, %2, %0;" : "+l"(d) : "l"(a), "l"(b));
}

// ---------------- persistent GEMM: out = act(X)[N,K] @ W[K,COUT] + b ------
template <int K, int COUT, int LAYER>
__global__ void __launch_bounds__(COUT * 4) k_gemm(
        const float* __restrict__ Xext,
        const float* __restrict__ W,
        const float* __restrict__ Bb,
        const float* __restrict__ gamma,
        const float* __restrict__ beta) {
    constexpr int TN = 4, TM = 4;
    constexpr int COLT = COUT / TN;       // 16 or 10
    constexpr int ROWT = 16;
    constexpr int RB   = ROWT * TM;       // 64 rows per tile
    constexpr int KC   = 32;
    constexpr int NTH  = COLT * ROWT;

    __shared__ __align__(16) float  Ws[K * COUT];
    __shared__ __align__(16) float  Bs[COUT];
    __shared__ __align__(16) float2 Xs2[RB][KC + 1];   // duplicated, padded
    __shared__ float sSc[64], sSh[64];

    const float* Xp = (LAYER == 1) ? Xext : g_hb;
    float* out = g_ha;

    const int tid  = threadIdx.x;
    const int colt = tid % COLT;
    const int rowt = tid / COLT;

    for (int idx = tid; idx < K * COUT; idx += NTH) Ws[idx] = W[idx];
    for (int idx = tid; idx < COUT; idx += NTH)     Bs[idx] = Bb[idx];
    if (LAYER != 1) {
        if (tid < K) {   // K == 64 for layers 2,3
            const float* acc = (LAYER == 2) ? g_bn1 : g_bn2;
            float inv_n = 1.0f / (float)NN;
            float mu  = acc[tid] * inv_n;
            float var = acc[64 + tid] * inv_n - mu * mu;
            float inv = rsqrtf(var + BN_EPS);
            float s = gamma[tid] * inv;
            sSc[tid] = s;
            sSh[tid] = fmaf(-mu, s, beta[tid]);
        }
    }
    __syncthreads();

    for (int tile = blockIdx.x; tile < NT_GEMM; tile += gridDim.x) {
        const int rowBase = tile * RB;

        unsigned long long a01[TM], a23[TM];
        #pragma unroll
        for (int i = 0; i < TM; i++) { a01[i] = 0ull; a23[i] = 0ull; }

        for (int k0 = 0; k0 < K; k0 += KC) {
            __syncthreads();
            for (int idx = tid; idx < RB * KC / 4; idx += NTH) {
                int r  = idx >> 3;
                int c4 = idx & 7;
                int gr = rowBase + r;
                float4 v = make_float4(0.f, 0.f, 0.f, 0.f);
                if (gr < NN)
                    v = *reinterpret_cast<const float4*>(&Xp[(long)gr * K + k0 + c4 * 4]);
                if (LAYER != 1) {
                    int kk = k0 + c4 * 4;
                    v.x = fmaxf(fmaf(v.x, sSc[kk    ], sSh[kk    ]), 0.f);
                    v.y = fmaxf(fmaf(v.y, sSc[kk + 1], sSh[kk + 1]), 0.f);
                    v.z = fmaxf(fmaf(v.z, sSc[kk + 2], sSh[kk + 2]), 0.f);
                    v.w = fmaxf(fmaf(v.w, sSc[kk + 3], sSh[kk + 3]), 0.f);
                }
                Xs2[r][c4 * 4    ] = make_float2(v.x, v.x);
                Xs2[r][c4 * 4 + 1] = make_float2(v.y, v.y);
                Xs2[r][c4 * 4 + 2] = make_float2(v.z, v.z);
                Xs2[r][c4 * 4 + 3] = make_float2(v.w, v.w);
            }
            __syncthreads();

            #pragma unroll
            for (int k = 0; k < KC; k++) {
                ulonglong2 w2 = *reinterpret_cast<const ulonglong2*>(
                    &Ws[(k0 + k) * COUT + colt * TN]);
                #pragma unroll
                for (int i = 0; i < TM; i++) {
                    unsigned long long xx = *reinterpret_cast<const unsigned long long*>(
                        &Xs2[rowt * TM + i][k]);
                    ffma2(a01[i], xx, w2.x);
                    ffma2(a23[i], xx, w2.y);
                }
            }
        }

        float4 b4 = *reinterpret_cast<const float4*>(&Bs[colt * TN]);
        #pragma unroll
        for (int i = 0; i < TM; i++) {
            int gr = rowBase + rowt * TM + i;
            if (gr < NN) {
                float2 p01 = *reinterpret_cast<float2*>(&a01[i]);
                float2 p23 = *reinterpret_cast<float2*>(&a23[i]);
                float4 o;
                o.x = p01.x + b4.x;
                o.y = p01.y + b4.y;
                o.z = p23.x + b4.z;
                o.w = p23.y + b4.w;
                *reinterpret_cast<float4*>(&out[(long)gr * COUT + colt * TN]) = o;
            }
        }
    }
}

// ---------------- aggregation C=64: warp/node, packed edges, unroll 8 ------
template <int LAYER>
__global__ void __launch_bounds__(256, 6) k_agg64() {
    const float2* __restrict__ h2 = reinterpret_cast<const float2*>(g_ha);
    float2* out2 = reinterpret_cast<float2*>(g_hb);
    float* bnacc = (LAYER == 1) ? g_bn1 : g_bn2;

    const int lane = threadIdx.x & 31;
    const int warp = threadIdx.x >> 5;
    const int nwarps = gridDim.x * 8;
    const int gw = blockIdx.x * 8 + warp;

    float sx = 0.f, sy = 0.f, qx = 0.f, qy = 0.f;

    for (int node = gw; node < NN; node += nwarps) {
        float dn = g_dis[node];
        float selfn = dn * dn;
        float2 a = h2[node * 32 + lane];
        a.x *= selfn; a.y *= selfn;
        float2 b = make_float2(0.f, 0.f);

        int j   = g_rowptr[node];
        int end = g_rowptr[node + 1];

        for (; j + 7 < end; j += 8) {
            int2 e0 = __ldg(&g_cedge[j  ]), e1 = __ldg(&g_cedge[j+1]);
            int2 e2 = __ldg(&g_cedge[j+2]), e3 = __ldg(&g_cedge[j+3]);
            int2 e4 = __ldg(&g_cedge[j+4]), e5 = __ldg(&g_cedge[j+5]);
            int2 e6 = __ldg(&g_cedge[j+6]), e7 = __ldg(&g_cedge[j+7]);
            float2 v0 = __ldg(&h2[e0.x * 32 + lane]);
            float2 v1 = __ldg(&h2[e1.x * 32 + lane]);
            float2 v2 = __ldg(&h2[e2.x * 32 + lane]);
            float2 v3 = __ldg(&h2[e3.x * 32 + lane]);
            float2 v4 = __ldg(&h2[e4.x * 32 + lane]);
            float2 v5 = __ldg(&h2[e5.x * 32 + lane]);
            float2 v6 = __ldg(&h2[e6.x * 32 + lane]);
            float2 v7 = __ldg(&h2[e7.x * 32 + lane]);
            float w0 = __int_as_float(e0.y), w1 = __int_as_float(e1.y);
            float w2 = __int_as_float(e2.y), w3 = __int_as_float(e3.y);
            float w4 = __int_as_float(e4.y), w5 = __int_as_float(e5.y);
            float w6 = __int_as_float(e6.y), w7 = __int_as_float(e7.y);
            a.x = fmaf(w0, v0.x, a.x); a.y = fmaf(w0, v0.y, a.y);
            b.x = fmaf(w1, v1.x, b.x); b.y = fmaf(w1, v1.y, b.y);
            a.x = fmaf(w2, v2.x, a.x); a.y = fmaf(w2, v2.y, a.y);
            b.x = fmaf(w3, v3.x, b.x); b.y = fmaf(w3, v3.y, b.y);
            a.x = fmaf(w4, v4.x, a.x); a.y = fmaf(w4, v4.y, a.y);
            b.x = fmaf(w5, v5.x, b.x); b.y = fmaf(w5, v5.y, b.y);
            a.x = fmaf(w6, v6.x, a.x); a.y = fmaf(w6, v6.y, a.y);
            b.x = fmaf(w7, v7.x, b.x); b.y = fmaf(w7, v7.y, b.y);
        }
        if (j + 3 < end) {
            int2 e0 = __ldg(&g_cedge[j  ]), e1 = __ldg(&g_cedge[j+1]);
            int2 e2 = __ldg(&g_cedge[j+2]), e3 = __ldg(&g_cedge[j+3]);
            float2 v0 = __ldg(&h2[e0.x * 32 + lane]);
            float2 v1 = __ldg(&h2[e1.x * 32 + lane]);
            float2 v2 = __ldg(&h2[e2.x * 32 + lane]);
            float2 v3 = __ldg(&h2[e3.x * 32 + lane]);
            float w0 = __int_as_float(e0.y), w1 = __int_as_float(e1.y);
            float w2 = __int_as_float(e2.y), w3 = __int_as_float(e3.y);
            a.x = fmaf(w0, v0.x, a.x); a.y = fmaf(w0, v0.y, a.y);
            b.x = fmaf(w1, v1.x, b.x); b.y = fmaf(w1, v1.y, b.y);
            a.x = fmaf(w2, v2.x, a.x); a.y = fmaf(w2, v2.y, a.y);
            b.x = fmaf(w3, v3.x, b.x); b.y = fmaf(w3, v3.y, b.y);
            j += 4;
        }
        if (j + 1 < end) {
            int2 e0 = __ldg(&g_cedge[j]), e1 = __ldg(&g_cedge[j+1]);
            float2 v0 = __ldg(&h2[e0.x * 32 + lane]);
            float2 v1 = __ldg(&h2[e1.x * 32 + lane]);
            float w0 = __int_as_float(e0.y), w1 = __int_as_float(e1.y);
            a.x = fmaf(w0, v0.x, a.x); a.y = fmaf(w0, v0.y, a.y);
            b.x = fmaf(w1, v1.x, b.x); b.y = fmaf(w1, v1.y, b.y);
            j += 2;
        }
        if (j < end) {
            int2 e = __ldg(&g_cedge[j]);
            float2 v = __ldg(&h2[e.x * 32 + lane]);
            float w = __int_as_float(e.y);
            a.x = fmaf(w, v.x, a.x); a.y = fmaf(w, v.y, a.y);
        }

        a.x += b.x; a.y += b.y;
        out2[node * 32 + lane] = a;
        sx += a.x; sy += a.y;
        qx += a.x * a.x; qy += a.y * a.y;
    }

    __shared__ float ss[64], sq[64];
    if (threadIdx.x < 64) { ss[threadIdx.x] = 0.f; sq[threadIdx.x] = 0.f; }
    __syncthreads();
    atomicAdd(&ss[2 * lane],     sx);
    atomicAdd(&ss[2 * lane + 1], sy);
    atomicAdd(&sq[2 * lane],     qx);
    atomicAdd(&sq[2 * lane + 1], qy);
    __syncthreads();
    if (threadIdx.x < 64) {
        atomicAdd(&bnacc[threadIdx.x],      ss[threadIdx.x]);
        atomicAdd(&bnacc[64 + threadIdx.x], sq[threadIdx.x]);
    }
}

// ---------------- aggregation C=40 (final, external out) + bn reset --------
__global__ void __launch_bounds__(256, 6) k_agg40(float* __restrict__ out) {
    constexpr int C = 40;
    const float* __restrict__ h = g_ha;

    const int lane = threadIdx.x & 31;
    const int warp = threadIdx.x >> 5;
    const int nwarps = gridDim.x * 8;
    const int gw = blockIdx.x * 8 + warp;
    const int c0 = lane;
    const int c1 = lane + 32;
    const bool has1 = (c1 < C);

    for (int node = gw; node < NN; node += nwarps) {
        float dn = g_dis[node];
        float selfn = dn * dn;
        float a0 = h[(long)node * C + c0] * selfn;
        float a1 = has1 ? h[(long)node * C + c1] * selfn : 0.f;
        float b0 = 0.f, b1 = 0.f;

        int j   = g_rowptr[node];
        int end = g_rowptr[node + 1];
        for (; j + 3 < end; j += 4) {
            int2 e0 = __ldg(&g_cedge[j  ]), e1 = __ldg(&g_cedge[j+1]);
            int2 e2 = __ldg(&g_cedge[j+2]), e3 = __ldg(&g_cedge[j+3]);
            float w0 = __int_as_float(e0.y), w1 = __int_as_float(e1.y);
            float w2 = __int_as_float(e2.y), w3 = __int_as_float(e3.y);
            float u0 = __ldg(&h[(long)e0.x * C + c0]);
            float u1 = __ldg(&h[(long)e1.x * C + c0]);
            float u2 = __ldg(&h[(long)e2.x * C + c0]);
            float u3 = __ldg(&h[(long)e3.x * C + c0]);
            a0 = fmaf(w0, u0, a0); b0 = fmaf(w1, u1, b0);
            a0 = fmaf(w2, u2, a0); b0 = fmaf(w3, u3, b0);
            if (has1) {
                float t0 = __ldg(&h[(long)e0.x * C + c1]);
                float t1 = __ldg(&h[(long)e1.x * C + c1]);
                float t2 = __ldg(&h[(long)e2.x * C + c1]);
                float t3 = __ldg(&h[(long)e3.x * C + c1]);
                a1 = fmaf(w0, t0, a1); b1 = fmaf(w1, t1, b1);
                a1 = fmaf(w2, t2, a1); b1 = fmaf(w3, t3, b1);
            }
        }
        for (; j < end; j++) {
            int2 e = __ldg(&g_cedge[j]);
            float w = __int_as_float(e.y);
            a0 = fmaf(w, __ldg(&h[(long)e.x * C + c0]), a0);
            if (has1) a1 = fmaf(w, __ldg(&h[(long)e.x * C + c1]), a1);
        }
        out[(long)node * C + c0] = a0 + b0;
        if (has1) out[(long)node * C + c1] = a1 + b1;
    }

    if (blockIdx.x == 0 && threadIdx.x < 128) {
        g_bn1[threadIdx.x] = 0.f;
        g_bn2[threadIdx.x] = 0.f;
    }
}

// ---------------- launch ----------------------------------------------------
extern "C" void kernel_launch(void* const* d_in, const int* in_sizes, int n_in,
                              void* d_out, int out_size) {
    const float* x  = (const float*)d_in[0];
    const int*   ei = (const int*)d_in[1];     // int32 (jax default)
    const float* W1 = (const float*)d_in[2];
    const float* b1 = (const float*)d_in[3];
    const float* g1 = (const float*)d_in[4];
    const float* be1= (const float*)d_in[5];
    const float* W2 = (const float*)d_in[6];
    const float* b2 = (const float*)d_in[7];
    const float* g2 = (const float*)d_in[8];
    const float* be2= (const float*)d_in[9];
    const float* W3 = (const float*)d_in[10];
    const float* b3 = (const float*)d_in[11];
    float* out = (float*)d_out;

    // side stream + events, created once (host-side only; no device mem)
    static cudaStream_t s2 = nullptr;
    static cudaEvent_t evFork = nullptr, evJoin = nullptr;
    if (s2 == nullptr) {
        cudaStreamCreateWithFlags(&s2, cudaStreamNonBlocking);
        cudaEventCreateWithFlags(&evFork, cudaEventDisableTiming);
        cudaEventCreateWithFlags(&evJoin, cudaEventDisableTiming);
    }

    // Fork: CSR build (s2) runs concurrently with GEMM layer 1 (main stream).
    cudaEventRecord(evFork, 0);
    cudaStreamWaitEvent(s2, evFork, 0);

    k_count<<<592, 256, 0, s2>>>(ei);
    k_scan<<<NSCAN, SCAN_TILE, 0, s2>>>();
    k_scatter<<<592, 256, 0, s2>>>(ei);

    k_gemm<128, 64, 1><<<592, 256>>>(x, W1, b1, nullptr, nullptr);

    // Join: aggregation needs both the CSR and the GEMM output.
    cudaEventRecord(evJoin, s2);
    cudaStreamWaitEvent(0, evJoin, 0);

    k_agg64<1><<<888, 256>>>();

    // layer 2 (BN1+ReLU fused into GEMM input load)
    k_gemm<64, 64, 2><<<888, 256>>>(nullptr, W2, b2, g1, be1);
    k_agg64<2><<<888, 256>>>();

    // layer 3 (BN2+ReLU fused), C_out = 40
    k_gemm<64, 40, 3><<<1184, 160>>>(nullptr, W3, b3, g2, be2);
    k_agg40<<<888, 256>>>(out);
}

// round 11
// speedup vs baseline: 1.0098x; 1.0098x over previous
#include <cuda_runtime.h>

// Problem constants
#define NN 100000
#define NE 1600000
constexpr float BN_EPS = 1e-5f;

constexpr int SCAN_TILE = 1024;
constexpr int NSCAN = (NN + SCAN_TILE - 1) / SCAN_TILE;   // 98
constexpr int NT_GEMM = (NN + 63) / 64;                   // 1563 row tiles

#define AGG_FLAG (1 << 30)
#define INC_FLAG (2 << 30)
#define VAL_MASK ((1 << 30) - 1)

// ---------------- scratch (static device globals; zero-initialized) -------
__device__ int   g_degcnt[NN];        // re-zeroed by k_scatter each replay
__device__ int   g_scanstate[NSCAN];  // re-zeroed by k_scatter each replay
__device__ float g_dis[NN];
__device__ int   g_rowptr[NN + 1];
__device__ int   g_fill[NN];
__device__ __align__(16) int2  g_cedge[NE];    // {src, float_bits(w)}
__device__ __align__(16) float g_ha[NN * 64];  // gemm outputs
__device__ __align__(16) float g_hb[NN * 64];  // agg outputs (layers 1,2)
__device__ float g_bn1[128];          // re-zeroed by k_agg40 each replay
__device__ float g_bn2[128];

// ---------------- degree count (int4-vectorized over dst half) ------------
__global__ void k_count(const int* __restrict__ ei) {
    const int4* d4 = reinterpret_cast<const int4*>(ei + NE);
    int i = blockIdx.x * blockDim.x + threadIdx.x;
    int stride = gridDim.x * blockDim.x;
    for (int e = i; e < NE / 4; e += stride) {
        int4 d = __ldg(&d4[e]);
        atomicAdd(&g_degcnt[d.x], 1);
        atomicAdd(&g_degcnt[d.y], 1);
        atomicAdd(&g_degcnt[d.z], 1);
        atomicAdd(&g_degcnt[d.w], 1);
    }
}

// ---------------- single-kernel scan, warp-parallel decoupled lookback -----
__global__ void k_scan() {
    __shared__ int sm[SCAN_TILE];
    __shared__ int s_prefix;
    const int t = threadIdx.x;
    const int b = blockIdx.x;
    const int i = b * SCAN_TILE + t;

    int v = (i < NN) ? g_degcnt[i] : 0;
    sm[t] = v;
    __syncthreads();
    #pragma unroll
    for (int off = 1; off < SCAN_TILE; off <<= 1) {
        int add = (t >= off) ? sm[t - off] : 0;
        __syncthreads();
        sm[t] += add;
        __syncthreads();
    }
    int incl = sm[t];
    int agg  = sm[SCAN_TILE - 1];

    if (t < 32) {
        if (b == 0) {
            if (t == 0) {
                atomicExch(&g_scanstate[0], INC_FLAG | agg);
                s_prefix = 0;
            }
        } else {
            if (t == 0) atomicExch(&g_scanstate[b], AGG_FLAG | agg);
            __syncwarp();
            int run = 0;
            int base = b;
            while (true) {
                int idx = base - 1 - t;
                int st = (idx >= 0) ? atomicAdd(&g_scanstate[idx], 0) : INC_FLAG;
                unsigned zero_b = __ballot_sync(0xffffffffu, st == 0);
                unsigned inc_b  = __ballot_sync(0xffffffffu, (st & INC_FLAG) != 0);
                if (inc_b != 0) {
                    int k = __ffs(inc_b) - 1;     // nearest INC lane
                    if ((zero_b & ((k == 31) ? 0xffffffffu : ((1u << (k + 1)) - 1))) == 0) {
                        int val = (t <= k) ? (st & VAL_MASK) : 0;
                        #pragma unroll
                        for (int o = 16; o > 0; o >>= 1)
                            val += __shfl_xor_sync(0xffffffffu, val, o);
                        run += val;
                        break;
                    }
                } else if (zero_b == 0) {
                    int val = st & VAL_MASK;
                    #pragma unroll
                    for (int o = 16; o > 0; o >>= 1)
                        val += __shfl_xor_sync(0xffffffffu, val, o);
                    run += val;
                    base -= 32;
                }
            }
            if (t == 0) {
                atomicExch(&g_scanstate[b], INC_FLAG | (run + agg));
                s_prefix = run;
            }
        }
    }
    __syncthreads();

    int excl = s_prefix + incl - v;
    if (i < NN) {
        g_rowptr[i] = excl;
        g_fill[i]   = excl;
        g_dis[i]    = rsqrtf((float)(v + 1));
    }
    if (i == 0) g_rowptr[NN] = NE;
}

// ---------------- CSR scatter (int4 loads) + state resets ------------------
__global__ void k_scatter(const int* __restrict__ ei) {
    const int4* s4 = reinterpret_cast<const int4*>(ei);
    const int4* d4 = reinterpret_cast<const int4*>(ei + NE);
    int i = blockIdx.x * blockDim.x + threadIdx.x;
    int stride = gridDim.x * blockDim.x;
    for (int e = i; e < NE / 4; e += stride) {
        int4 s = __ldg(&s4[e]);
        int4 d = __ldg(&d4[e]);
        {
            float w = g_dis[s.x] * g_dis[d.x];
            g_cedge[atomicAdd(&g_fill[d.x], 1)] = make_int2(s.x, __float_as_int(w));
        }
        {
            float w = g_dis[s.y] * g_dis[d.y];
            g_cedge[atomicAdd(&g_fill[d.y], 1)] = make_int2(s.y, __float_as_int(w));
        }
        {
            float w = g_dis[s.z] * g_dis[d.z];
            g_cedge[atomicAdd(&g_fill[d.z], 1)] = make_int2(s.z, __float_as_int(w));
        }
        {
            float w = g_dis[s.w] * g_dis[d.w];
            g_cedge[atomicAdd(&g_fill[d.w], 1)] = make_int2(s.w, __float_as_int(w));
        }
    }
    for (int n = i; n < NN; n += stride) g_degcnt[n] = 0;
    if (i < NSCAN) g_scanstate[i] = 0;
}

// ---------------- f32x2 helper ---------------------------------------------
__device__ __forceinline__ void ffma2(unsigned long long& d,
                                      unsigned long long a,
                                      unsigned long long b) {
    asm("fma.rn.f32x2 %0, %1, %2, %0;" : "+l"(d) : "l"(a), "l"(b));
}

// ---------------- persistent GEMM: out = act(X)[N,K] @ W[K,COUT] + b ------
// TM=4 rows/thread, TN cols/thread (4 or 8). Duplicated-X shared tile.
template <int K, int COUT, int TN, int LAYER>
__global__ void __launch_bounds__((COUT / TN) * 16) k_gemm(
        const float* __restrict__ Xext,
        const float* __restrict__ W,
        const float* __restrict__ Bb,
        const float* __restrict__ gamma,
        const float* __restrict__ beta) {
    constexpr int TM = 4;
    constexpr int COLT = COUT / TN;       // 8 or 10
    constexpr int ROWT = 16;
    constexpr int RB   = ROWT * TM;       // 64 rows per tile
    constexpr int KC   = 32;
    constexpr int NTH  = COLT * ROWT;
    constexpr int TNH  = TN / 2;

    __shared__ __align__(16) float  Ws[K * COUT];
    __shared__ __align__(16) float  Bs[COUT];
    __shared__ __align__(16) float2 Xs2[RB][KC + 1];   // duplicated, padded
    __shared__ float sSc[64], sSh[64];

    const float* Xp = (LAYER == 1) ? Xext : g_hb;
    float* out = g_ha;

    const int tid  = threadIdx.x;
    const int colt = tid % COLT;
    const int rowt = tid / COLT;

    for (int idx = tid; idx < K * COUT; idx += NTH) Ws[idx] = W[idx];
    for (int idx = tid; idx < COUT; idx += NTH)     Bs[idx] = Bb[idx];
    if (LAYER != 1) {
        if (tid < K) {   // K == 64 for layers 2,3
            const float* acc = (LAYER == 2) ? g_bn1 : g_bn2;
            float inv_n = 1.0f / (float)NN;
            float mu  = acc[tid] * inv_n;
            float var = acc[64 + tid] * inv_n - mu * mu;
            float inv = rsqrtf(var + BN_EPS);
            float s = gamma[tid] * inv;
            sSc[tid] = s;
            sSh[tid] = fmaf(-mu, s, beta[tid]);
        }
    }
    __syncthreads();

    for (int tile = blockIdx.x; tile < NT_GEMM; tile += gridDim.x) {
        const int rowBase = tile * RB;

        unsigned long long acc[TM][TNH];
        #pragma unroll
        for (int i = 0; i < TM; i++)
            #pragma unroll
            for (int t = 0; t < TNH; t++) acc[i][t] = 0ull;

        for (int k0 = 0; k0 < K; k0 += KC) {
            __syncthreads();
            for (int idx = tid; idx < RB * KC / 4; idx += NTH) {
                int r  = idx >> 3;
                int c4 = idx & 7;
                int gr = rowBase + r;
                float4 v = make_float4(0.f, 0.f, 0.f, 0.f);
                if (gr < NN)
                    v = *reinterpret_cast<const float4*>(&Xp[(long)gr * K + k0 + c4 * 4]);
                if (LAYER != 1) {
                    int kk = k0 + c4 * 4;
                    v.x = fmaxf(fmaf(v.x, sSc[kk    ], sSh[kk    ]), 0.f);
                    v.y = fmaxf(fmaf(v.y, sSc[kk + 1], sSh[kk + 1]), 0.f);
                    v.z = fmaxf(fmaf(v.z, sSc[kk + 2], sSh[kk + 2]), 0.f);
                    v.w = fmaxf(fmaf(v.w, sSc[kk + 3], sSh[kk + 3]), 0.f);
                }
                Xs2[r][c4 * 4    ] = make_float2(v.x, v.x);
                Xs2[r][c4 * 4 + 1] = make_float2(v.y, v.y);
                Xs2[r][c4 * 4 + 2] = make_float2(v.z, v.z);
                Xs2[r][c4 * 4 + 3] = make_float2(v.w, v.w);
            }
            __syncthreads();

            #pragma unroll
            for (int k = 0; k < KC; k++) {
                unsigned long long wv[TNH];
                if (TN == 8) {
                    ulonglong2 q0 = *reinterpret_cast<const ulonglong2*>(
                        &Ws[(k0 + k) * COUT + colt * TN]);
                    ulonglong2 q1 = *reinterpret_cast<const ulonglong2*>(
                        &Ws[(k0 + k) * COUT + colt * TN + 4]);
                    wv[0] = q0.x; wv[1] = q0.y;
                    wv[2 % TNH] = q1.x; wv[3 % TNH] = q1.y;   // (TNH==4 here)
                } else {
                    ulonglong2 q = *reinterpret_cast<const ulonglong2*>(
                        &Ws[(k0 + k) * COUT + colt * TN]);
                    wv[0] = q.x; wv[1 % TNH] = q.y;
                }
                #pragma unroll
                for (int i = 0; i < TM; i++) {
                    unsigned long long xx = *reinterpret_cast<const unsigned long long*>(
                        &Xs2[rowt * TM + i][k]);
                    #pragma unroll
                    for (int t = 0; t < TNH; t++) ffma2(acc[i][t], xx, wv[t]);
                }
            }
        }

        #pragma unroll
        for (int i = 0; i < TM; i++) {
            int gr = rowBase + rowt * TM + i;
            if (gr < NN) {
                #pragma unroll
                for (int tt = 0; tt < TN / 4; tt++) {
                    float4 bq = *reinterpret_cast<const float4*>(&Bs[colt * TN + tt * 4]);
                    float2 p0 = *reinterpret_cast<float2*>(&acc[i][tt * 2]);
                    float2 p1 = *reinterpret_cast<float2*>(&acc[i][tt * 2 + 1]);
                    float4 o;
                    o.x = p0.x + bq.x;
                    o.y = p0.y + bq.y;
                    o.z = p1.x + bq.z;
                    o.w = p1.y + bq.w;
                    *reinterpret_cast<float4*>(
                        &out[(long)gr * COUT + colt * TN + tt * 4]) = o;
                }
            }
        }
    }
}

// ---------------- aggregation C=64: half-warp per edge, float4 lanes -------
template <int LAYER>
__global__ void __launch_bounds__(256, 6) k_agg64() {
    const float4* __restrict__ h4 = reinterpret_cast<const float4*>(g_ha);
    float4* out4 = reinterpret_cast<float4*>(g_hb);
    float* bnacc = (LAYER == 1) ? g_bn1 : g_bn2;

    const int lane = threadIdx.x & 31;
    const int warp = threadIdx.x >> 5;
    const int nwarps = gridDim.x * 8;
    const int gw = blockIdx.x * 8 + warp;
    const int g  = lane >> 4;        // edge-parity group (0/1)
    const int cl = lane & 15;        // float4 channel quad

    float4 stat_s = make_float4(0.f, 0.f, 0.f, 0.f);
    float4 stat_q = make_float4(0.f, 0.f, 0.f, 0.f);

    for (int node = gw; node < NN; node += nwarps) {
        float dn = g_dis[node];
        float selfn = dn * dn;
        float4 a = make_float4(0.f, 0.f, 0.f, 0.f);
        float4 b = make_float4(0.f, 0.f, 0.f, 0.f);
        if (g == 0) {
            float4 hs = h4[node * 16 + cl];
            a.x = hs.x * selfn; a.y = hs.y * selfn;
            a.z = hs.z * selfn; a.w = hs.w * selfn;
        }
        int j   = g_rowptr[node] + g;
        int end = g_rowptr[node + 1];
        for (; j + 2 < end; j += 4) {
            int2 e0 = __ldg(&g_cedge[j]);
            int2 e1 = __ldg(&g_cedge[j + 2]);
            float4 v0 = __ldg(&h4[e0.x * 16 + cl]);
            float4 v1 = __ldg(&h4[e1.x * 16 + cl]);
            float w0 = __int_as_float(e0.y);
            float w1 = __int_as_float(e1.y);
            a.x = fmaf(w0, v0.x, a.x); a.y = fmaf(w0, v0.y, a.y);
            a.z = fmaf(w0, v0.z, a.z); a.w = fmaf(w0, v0.w, a.w);
            b.x = fmaf(w1, v1.x, b.x); b.y = fmaf(w1, v1.y, b.y);
            b.z = fmaf(w1, v1.z, b.z); b.w = fmaf(w1, v1.w, b.w);
        }
        if (j < end) {
            int2 e = __ldg(&g_cedge[j]);
            float4 v = __ldg(&h4[e.x * 16 + cl]);
            float w = __int_as_float(e.y);
            a.x = fmaf(w, v.x, a.x); a.y = fmaf(w, v.y, a.y);
            a.z = fmaf(w, v.z, a.z); a.w = fmaf(w, v.w, a.w);
        }
        a.x += b.x; a.y += b.y; a.z += b.z; a.w += b.w;
        __syncwarp();
        a.x += __shfl_xor_sync(0xffffffffu, a.x, 16);
        a.y += __shfl_xor_sync(0xffffffffu, a.y, 16);
        a.z += __shfl_xor_sync(0xffffffffu, a.z, 16);
        a.w += __shfl_xor_sync(0xffffffffu, a.w, 16);
        if (g == 0) {
            out4[node * 16 + cl] = a;
            stat_s.x += a.x; stat_s.y += a.y; stat_s.z += a.z; stat_s.w += a.w;
            stat_q.x += a.x * a.x; stat_q.y += a.y * a.y;
            stat_q.z += a.z * a.z; stat_q.w += a.w * a.w;
        }
    }

    __shared__ float ss[64], sq[64];
    if (threadIdx.x < 64) { ss[threadIdx.x] = 0.f; sq[threadIdx.x] = 0.f; }
    __syncthreads();
    if (g == 0) {
        atomicAdd(&ss[cl * 4    ], stat_s.x);
        atomicAdd(&ss[cl * 4 + 1], stat_s.y);
        atomicAdd(&ss[cl * 4 + 2], stat_s.z);
        atomicAdd(&ss[cl * 4 + 3], stat_s.w);
        atomicAdd(&sq[cl * 4    ], stat_q.x);
        atomicAdd(&sq[cl * 4 + 1], stat_q.y);
        atomicAdd(&sq[cl * 4 + 2], stat_q.z);
        atomicAdd(&sq[cl * 4 + 3], stat_q.w);
    }
    __syncthreads();
    if (threadIdx.x < 64) {
        atomicAdd(&bnacc[threadIdx.x],      ss[threadIdx.x]);
        atomicAdd(&bnacc[64 + threadIdx.x], sq[threadIdx.x]);
    }
}

// ---------------- aggregation C=40: 3 groups of 10 lanes, float4 -----------
__global__ void __launch_bounds__(256, 6) k_agg40(float* __restrict__ out) {
    const float4* __restrict__ h4 = reinterpret_cast<const float4*>(g_ha);
    float4* out4 = reinterpret_cast<float4*>(out);

    const int lane = threadIdx.x & 31;
    const int warp = threadIdx.x >> 5;
    const int nwarps = gridDim.x * 8;
    const int gw = blockIdx.x * 8 + warp;
    const int g  = lane / 10;            // 0,1,2 active; 3 = idle lanes 30,31
    const int cl = lane - g * 10;
    const bool active = (lane < 30);

    for (int node = gw; node < NN; node += nwarps) {
        float dn = g_dis[node];
        float selfn = dn * dn;
        float4 a = make_float4(0.f, 0.f, 0.f, 0.f);
        float4 b = make_float4(0.f, 0.f, 0.f, 0.f);
        if (g == 0) {
            float4 hs = h4[node * 10 + cl];
            a.x = hs.x * selfn; a.y = hs.y * selfn;
            a.z = hs.z * selfn; a.w = hs.w * selfn;
        }
        int end = g_rowptr[node + 1];
        int j   = active ? (g_rowptr[node] + g) : end;
        for (; j + 3 < end; j += 6) {
            int2 e0 = __ldg(&g_cedge[j]);
            int2 e1 = __ldg(&g_cedge[j + 3]);
            float4 v0 = __ldg(&h4[e0.x * 10 + cl]);
            float4 v1 = __ldg(&h4[e1.x * 10 + cl]);
            float w0 = __int_as_float(e0.y);
            float w1 = __int_as_float(e1.y);
            a.x = fmaf(w0, v0.x, a.x); a.y = fmaf(w0, v0.y, a.y);
            a.z = fmaf(w0, v0.z, a.z); a.w = fmaf(w0, v0.w, a.w);
            b.x = fmaf(w1, v1.x, b.x); b.y = fmaf(w1, v1.y, b.y);
            b.z = fmaf(w1, v1.z, b.z); b.w = fmaf(w1, v1.w, b.w);
        }
        if (j < end) {
            int2 e = __ldg(&g_cedge[j]);
            float4 v = __ldg(&h4[e.x * 10 + cl]);
            float w = __int_as_float(e.y);
            a.x = fmaf(w, v.x, a.x); a.y = fmaf(w, v.y, a.y);
            a.z = fmaf(w, v.z, a.z); a.w = fmaf(w, v.w, a.w);
        }
        a.x += b.x; a.y += b.y; a.z += b.z; a.w += b.w;
        __syncwarp();
        float4 t1, t2;
        t1.x = __shfl_down_sync(0xffffffffu, a.x, 10);
        t1.y = __shfl_down_sync(0xffffffffu, a.y, 10);
        t1.z = __shfl_down_sync(0xffffffffu, a.z, 10);
        t1.w = __shfl_down_sync(0xffffffffu, a.w, 10);
        t2.x = __shfl_down_sync(0xffffffffu, a.x, 20);
        t2.y = __shfl_down_sync(0xffffffffu, a.y, 20);
        t2.z = __shfl_down_sync(0xffffffffu, a.z, 20);
        t2.w = __shfl_down_sync(0xffffffffu, a.w, 20);
        if (g == 0) {
            a.x += t1.x + t2.x; a.y += t1.y + t2.y;
            a.z += t1.z + t2.z; a.w += t1.w + t2.w;
            out4[node * 10 + cl] = a;
        }
    }

    // reset BN accumulators for the next replay (already consumed)
    if (blockIdx.x == 0 && threadIdx.x < 128) {
        g_bn1[threadIdx.x] = 0.f;
        g_bn2[threadIdx.x] = 0.f;
    }
}

// ---------------- launch (sequential — overlap regressed in R10) -----------
extern "C" void kernel_launch(void* const* d_in, const int* in_sizes, int n_in,
                              void* d_out, int out_size) {
    const float* x  = (const float*)d_in[0];
    const int*   ei = (const int*)d_in[1];     // int32 (jax default)
    const float* W1 = (const float*)d_in[2];
    const float* b1 = (const float*)d_in[3];
    const float* g1 = (const float*)d_in[4];
    const float* be1= (const float*)d_in[5];
    const float* W2 = (const float*)d_in[6];
    const float* b2 = (const float*)d_in[7];
    const float* g2 = (const float*)d_in[8];
    const float* be2= (const float*)d_in[9];
    const float* W3 = (const float*)d_in[10];
    const float* b3 = (const float*)d_in[11];
    float* out = (float*)d_out;

    // graph construction (CSR by dst) + norms
    k_count<<<592, 256>>>(ei);
    k_scan<<<NSCAN, SCAN_TILE>>>();
    k_scatter<<<592, 256>>>(ei);

    // layer 1
    k_gemm<128, 64, 8, 1><<<592, 128>>>(x, W1, b1, nullptr, nullptr);
    k_agg64<1><<<888, 256>>>();

    // layer 2 (BN1+ReLU fused into GEMM input load)
    k_gemm<64, 64, 8, 2><<<888, 128>>>(nullptr, W2, b2, g1, be1);
    k_agg64<2><<<888, 256>>>();

    // layer 3 (BN2+ReLU fused), C_out = 40
    k_gemm<64, 40, 4, 3><<<592, 160>>>(nullptr, W3, b3, g2, be2);
    k_agg40<<<888, 256>>>(out);
}

// round 14
// speedup vs baseline: 1.2248x; 1.2129x over previous
#include <cuda_runtime.h>

// Problem constants
#define NN 100000
#define NE 1600000
constexpr float BN_EPS = 1e-5f;

constexpr int SCAN_TILE = 1024;
constexpr int NSCAN = (NN + SCAN_TILE - 1) / SCAN_TILE;   // 98
constexpr int NT_GEMM = (NN + 63) / 64;                   // 1563 row tiles

#define AGG_FLAG (1 << 30)
#define INC_FLAG (2 << 30)
#define VAL_MASK ((1 << 30) - 1)

// ---------------- scratch (static device globals; zero-initialized) -------
__device__ int   g_degcnt[NN];        // re-zeroed by k_scatter each replay
__device__ int   g_scanstate[NSCAN];  // re-zeroed by k_scatter each replay
__device__ float g_dis[NN];
__device__ int   g_rowptr[NN + 1];
__device__ int   g_fill[NN];
__device__ __align__(16) int2  g_cedge[NE];    // {src, float_bits(w)}
__device__ __align__(16) float g_ha[NN * 64];  // gemm outputs
__device__ __align__(16) float g_hb[NN * 64];  // agg outputs (layers 1,2)
__device__ float g_bn1[128];          // re-zeroed by k_agg40 each replay
__device__ float g_bn2[128];

// ---------------- degree count (int4-vectorized over dst half) ------------
__global__ void k_count(const int* __restrict__ ei) {
    const int4* d4 = reinterpret_cast<const int4*>(ei + NE);
    int i = blockIdx.x * blockDim.x + threadIdx.x;
    int stride = gridDim.x * blockDim.x;
    for (int e = i; e < NE / 4; e += stride) {
        int4 d = __ldg(&d4[e]);
        atomicAdd(&g_degcnt[d.x], 1);
        atomicAdd(&g_degcnt[d.y], 1);
        atomicAdd(&g_degcnt[d.z], 1);
        atomicAdd(&g_degcnt[d.w], 1);
    }
}

// ---------------- single-kernel scan, warp-parallel decoupled lookback -----
__global__ void k_scan() {
    __shared__ int sm[SCAN_TILE];
    __shared__ int s_prefix;
    const int t = threadIdx.x;
    const int b = blockIdx.x;
    const int i = b * SCAN_TILE + t;

    int v = (i < NN) ? g_degcnt[i] : 0;
    sm[t] = v;
    __syncthreads();
    #pragma unroll
    for (int off = 1; off < SCAN_TILE; off <<= 1) {
        int add = (t >= off) ? sm[t - off] : 0;
        __syncthreads();
        sm[t] += add;
        __syncthreads();
    }
    int incl = sm[t];
    int agg  = sm[SCAN_TILE - 1];

    if (t < 32) {
        if (b == 0) {
            if (t == 0) {
                atomicExch(&g_scanstate[0], INC_FLAG | agg);
                s_prefix = 0;
            }
        } else {
            if (t == 0) atomicExch(&g_scanstate[b], AGG_FLAG | agg);
            __syncwarp();
            int run = 0;
            int base = b;
            while (true) {
                int idx = base - 1 - t;
                int st = (idx >= 0) ? atomicAdd(&g_scanstate[idx], 0) : INC_FLAG;
                unsigned zero_b = __ballot_sync(0xffffffffu, st == 0);
                unsigned inc_b  = __ballot_sync(0xffffffffu, (st & INC_FLAG) != 0);
                if (inc_b != 0) {
                    int k = __ffs(inc_b) - 1;     // nearest INC lane
                    if ((zero_b & ((k == 31) ? 0xffffffffu : ((1u << (k + 1)) - 1))) == 0) {
                        int val = (t <= k) ? (st & VAL_MASK) : 0;
                        #pragma unroll
                        for (int o = 16; o > 0; o >>= 1)
                            val += __shfl_xor_sync(0xffffffffu, val, o);
                        run += val;
                        break;
                    }
                } else if (zero_b == 0) {
                    int val = st & VAL_MASK;
                    #pragma unroll
                    for (int o = 16; o > 0; o >>= 1)
                        val += __shfl_xor_sync(0xffffffffu, val, o);
                    run += val;
                    base -= 32;
                }
            }
            if (t == 0) {
                atomicExch(&g_scanstate[b], INC_FLAG | (run + agg));
                s_prefix = run;
            }
        }
    }
    __syncthreads();

    int excl = s_prefix + incl - v;
    if (i < NN) {
        g_rowptr[i] = excl;
        g_fill[i]   = excl;
        g_dis[i]    = rsqrtf((float)(v + 1));
    }
    if (i == 0) g_rowptr[NN] = NE;
}

// ---------------- CSR scatter (int4 loads) + state resets ------------------
__global__ void k_scatter(const int* __restrict__ ei) {
    const int4* s4 = reinterpret_cast<const int4*>(ei);
    const int4* d4 = reinterpret_cast<const int4*>(ei + NE);
    int i = blockIdx.x * blockDim.x + threadIdx.x;
    int stride = gridDim.x * blockDim.x;
    for (int e = i; e < NE / 4; e += stride) {
        int4 s = __ldg(&s4[e]);
        int4 d = __ldg(&d4[e]);
        {
            float w = g_dis[s.x] * g_dis[d.x];
            g_cedge[atomicAdd(&g_fill[d.x], 1)] = make_int2(s.x, __float_as_int(w));
        }
        {
            float w = g_dis[s.y] * g_dis[d.y];
            g_cedge[atomicAdd(&g_fill[d.y], 1)] = make_int2(s.y, __float_as_int(w));
        }
        {
            float w = g_dis[s.z] * g_dis[d.z];
            g_cedge[atomicAdd(&g_fill[d.z], 1)] = make_int2(s.z, __float_as_int(w));
        }
        {
            float w = g_dis[s.w] * g_dis[d.w];
            g_cedge[atomicAdd(&g_fill[d.w], 1)] = make_int2(s.w, __float_as_int(w));
        }
    }
    for (int n = i; n < NN; n += stride) g_degcnt[n] = 0;
    if (i < NSCAN) g_scanstate[i] = 0;
}

// ---------------- f32x2 helpers --------------------------------------------
__device__ __forceinline__ void ffma2(unsigned long long& d,
                                      unsigned long long a,
                                      unsigned long long b) {
    asm("fma.rn.f32x2 %0, %1, %2, %0;" : "+l"(d) : "l"(a), "l"(b));
}
__device__ __forceinline__ unsigned long long dup2(float x) {
    unsigned long long r;
    asm("mov.b64 %0, {%1, %1};" : "=l"(r) : "r"(__float_as_int(x)));
    return r;
}

// ---------------- persistent GEMM, k-unrolled x4, double-buffered X --------
// DYNAMIC shared memory (static 48KB limit overflows for K=128).
// Layout (floats): Ws[K*COUT] | Bs[COUT] | sSc[64] | sSh[64] | Xs[2][RB*XSTR]
template <int K, int COUT, int LAYER>
__global__ void __launch_bounds__((COUT / 4) * 16, 4) k_gemm(
        const float* __restrict__ Xext,
        const float* __restrict__ W,
        const float* __restrict__ Bb,
        const float* __restrict__ gamma,
        const float* __restrict__ beta) {
    constexpr int TM = 4, TN = 4;
    constexpr int COLT = COUT / TN;       // 16 or 10
    constexpr int ROWT = 16;
    constexpr int RB   = ROWT * TM;       // 64 rows per tile
    constexpr int KC   = 32;
    constexpr int NCH  = K / KC;          // chunks per tile (4 or 2)
    constexpr int NTH  = COLT * ROWT;
    constexpr int XSTR = KC + 4;          // 36: 16B-aligned rows, rows 4 apart
                                          // -> +16 banks (conflict-free)

    extern __shared__ __align__(16) float smem_dyn[];
    float* Ws  = smem_dyn;                       // K*COUT
    float* Bs  = Ws + K * COUT;                  // COUT
    float* sSc = Bs + COUT;                      // 64
    float* sSh = sSc + 64;                       // 64
    float* Xs0 = sSh + 64;                       // RB*XSTR
    float* Xs1 = Xs0 + RB * XSTR;                // RB*XSTR
    float* Xbuf[2] = { Xs0, Xs1 };

    const float* Xp = (LAYER == 1) ? Xext : g_hb;
    float* out = g_ha;

    const int tid  = threadIdx.x;
    const int colt = tid % COLT;
    const int rowt = tid / COLT;

    for (int idx = tid; idx < K * COUT; idx += NTH) Ws[idx] = W[idx];
    for (int idx = tid; idx < COUT; idx += NTH)     Bs[idx] = Bb[idx];
    if (LAYER != 1) {
        if (tid < K) {   // K == 64 for layers 2,3
            const float* acc = (LAYER == 2) ? g_bn1 : g_bn2;
            float inv_n = 1.0f / (float)NN;
            float mu  = acc[tid] * inv_n;
            float var = acc[64 + tid] * inv_n - mu * mu;
            float inv = rsqrtf(var + BN_EPS);
            float s = gamma[tid] * inv;
            sSc[tid] = s;
            sSh[tid] = fmaf(-mu, s, beta[tid]);
        }
    }
    // BUGFIX (R13): sSc/sSh (and Ws/Bs) must be visible to ALL threads
    // before the first stage() reads them. This barrier was missing.
    __syncthreads();

    // stage one 64x32 X chunk (plain floats) into Xbuf[buf]
    auto stage = [&](int tile, int chunk, int buf) {
        const int rowBase = tile * RB;
        const int k0 = chunk * KC;
        for (int idx = tid; idx < RB * (KC / 4); idx += NTH) {
            int r  = idx >> 3;          // KC/4 == 8 float4 per row
            int c4 = idx & 7;
            int gr = rowBase + r;
            float4 v = make_float4(0.f, 0.f, 0.f, 0.f);
            if (gr < NN)
                v = *reinterpret_cast<const float4*>(&Xp[(long)gr * K + k0 + c4 * 4]);
            if (LAYER != 1) {
                int kk = k0 + c4 * 4;
                v.x = fmaxf(fmaf(v.x, sSc[kk    ], sSh[kk    ]), 0.f);
                v.y = fmaxf(fmaf(v.y, sSc[kk + 1], sSh[kk + 1]), 0.f);
                v.z = fmaxf(fmaf(v.z, sSc[kk + 2], sSh[kk + 2]), 0.f);
                v.w = fmaxf(fmaf(v.w, sSc[kk + 3], sSh[kk + 3]), 0.f);
            }
            *reinterpret_cast<float4*>(&Xbuf[buf][r * XSTR + c4 * 4]) = v;
        }
    };

    int tile = blockIdx.x;
    int buf = 0;
    if (tile < NT_GEMM) stage(tile, 0, 0);
    __syncthreads();

    for (; tile < NT_GEMM; tile += gridDim.x) {
        const int rowBase = tile * RB;

        unsigned long long acc[TM][2];
        #pragma unroll
        for (int i = 0; i < TM; i++) { acc[i][0] = 0ull; acc[i][1] = 0ull; }

        #pragma unroll
        for (int chunk = 0; chunk < NCH; chunk++) {
            // prefetch next chunk (possibly of next tile) into other buffer
            {
                int ntile  = (chunk + 1 < NCH) ? tile : tile + gridDim.x;
                int nchunk = (chunk + 1 < NCH) ? chunk + 1 : 0;
                if (ntile < NT_GEMM) stage(ntile, nchunk, buf ^ 1);
            }
            const int k0 = chunk * KC;
            const float* xbase = &Xbuf[buf][rowt * TM * XSTR];

            #pragma unroll
            for (int k4 = 0; k4 < KC / 4; k4++) {
                float4 xr[TM];
                #pragma unroll
                for (int i = 0; i < TM; i++)
                    xr[i] = *reinterpret_cast<const float4*>(&xbase[i * XSTR + k4 * 4]);
                #pragma unroll
                for (int kk = 0; kk < 4; kk++) {
                    ulonglong2 w = *reinterpret_cast<const ulonglong2*>(
                        &Ws[(k0 + k4 * 4 + kk) * COUT + colt * TN]);
                    #pragma unroll
                    for (int i = 0; i < TM; i++) {
                        float xv = (kk == 0) ? xr[i].x : (kk == 1) ? xr[i].y
                                 : (kk == 2) ? xr[i].z : xr[i].w;
                        unsigned long long xx = dup2(xv);
                        ffma2(acc[i][0], xx, w.x);
                        ffma2(acc[i][1], xx, w.y);
                    }
                }
            }
            __syncthreads();
            buf ^= 1;
        }

        float4 b4 = *reinterpret_cast<const float4*>(&Bs[colt * TN]);
        #pragma unroll
        for (int i = 0; i < TM; i++) {
            int gr = rowBase + rowt * TM + i;
            if (gr < NN) {
                float2 p01 = *reinterpret_cast<float2*>(&acc[i][0]);
                float2 p23 = *reinterpret_cast<float2*>(&acc[i][1]);
                float4 o;
                o.x = p01.x + b4.x;
                o.y = p01.y + b4.y;
                o.z = p23.x + b4.z;
                o.w = p23.y + b4.w;
                *reinterpret_cast<float4*>(&out[(long)gr * COUT + colt * TN]) = o;
            }
        }
    }
}

// dynamic smem byte counts per instantiation
constexpr int gemm_smem(int K, int COUT) {
    return (K * COUT + COUT + 128 + 2 * 64 * 36) * (int)sizeof(float);
}

// ---------------- aggregation C=64: half-warp per edge, float4 lanes -------
template <int LAYER>
__global__ void __launch_bounds__(256, 6) k_agg64() {
    const float4* __restrict__ h4 = reinterpret_cast<const float4*>(g_ha);
    float4* out4 = reinterpret_cast<float4*>(g_hb);
    float* bnacc = (LAYER == 1) ? g_bn1 : g_bn2;

    const int lane = threadIdx.x & 31;
    const int warp = threadIdx.x >> 5;
    const int nwarps = gridDim.x * 8;
    const int gw = blockIdx.x * 8 + warp;
    const int g  = lane >> 4;        // edge-parity group (0/1)
    const int cl = lane & 15;        // float4 channel quad

    float4 stat_s = make_float4(0.f, 0.f, 0.f, 0.f);
    float4 stat_q = make_float4(0.f, 0.f, 0.f, 0.f);

    for (int node = gw; node < NN; node += nwarps) {
        float dn = g_dis[node];
        float selfn = dn * dn;
        float4 a = make_float4(0.f, 0.f, 0.f, 0.f);
        float4 b = make_float4(0.f, 0.f, 0.f, 0.f);
        if (g == 0) {
            float4 hs = h4[node * 16 + cl];
            a.x = hs.x * selfn; a.y = hs.y * selfn;
            a.z = hs.z * selfn; a.w = hs.w * selfn;
        }
        int j   = g_rowptr[node] + g;
        int end = g_rowptr[node + 1];
        for (; j + 2 < end; j += 4) {
            int2 e0 = __ldg(&g_cedge[j]);
            int2 e1 = __ldg(&g_cedge[j + 2]);
            float4 v0 = __ldg(&h4[e0.x * 16 + cl]);
            float4 v1 = __ldg(&h4[e1.x * 16 + cl]);
            float w0 = __int_as_float(e0.y);
            float w1 = __int_as_float(e1.y);
            a.x = fmaf(w0, v0.x, a.x); a.y = fmaf(w0, v0.y, a.y);
            a.z = fmaf(w0, v0.z, a.z); a.w = fmaf(w0, v0.w, a.w);
            b.x = fmaf(w1, v1.x, b.x); b.y = fmaf(w1, v1.y, b.y);
            b.z = fmaf(w1, v1.z, b.z); b.w = fmaf(w1, v1.w, b.w);
        }
        if (j < end) {
            int2 e = __ldg(&g_cedge[j]);
            float4 v = __ldg(&h4[e.x * 16 + cl]);
            float w = __int_as_float(e.y);
            a.x = fmaf(w, v.x, a.x); a.y = fmaf(w, v.y, a.y);
            a.z = fmaf(w, v.z, a.z); a.w = fmaf(w, v.w, a.w);
        }
        a.x += b.x; a.y += b.y; a.z += b.z; a.w += b.w;
        __syncwarp();
        a.x += __shfl_xor_sync(0xffffffffu, a.x, 16);
        a.y += __shfl_xor_sync(0xffffffffu, a.y, 16);
        a.z += __shfl_xor_sync(0xffffffffu, a.z, 16);
        a.w += __shfl_xor_sync(0xffffffffu, a.w, 16);
        if (g == 0) {
            out4[node * 16 + cl] = a;
            stat_s.x += a.x; stat_s.y += a.y; stat_s.z += a.z; stat_s.w += a.w;
            stat_q.x += a.x * a.x; stat_q.y += a.y * a.y;
            stat_q.z += a.z * a.z; stat_q.w += a.w * a.w;
        }
    }

    __shared__ float ss[64], sq[64];
    if (threadIdx.x < 64) { ss[threadIdx.x] = 0.f; sq[threadIdx.x] = 0.f; }
    __syncthreads();
    if (g == 0) {
        atomicAdd(&ss[cl * 4    ], stat_s.x);
        atomicAdd(&ss[cl * 4 + 1], stat_s.y);
        atomicAdd(&ss[cl * 4 + 2], stat_s.z);
        atomicAdd(&ss[cl * 4 + 3], stat_s.w);
        atomicAdd(&sq[cl * 4    ], stat_q.x);
        atomicAdd(&sq[cl * 4 + 1], stat_q.y);
        atomicAdd(&sq[cl * 4 + 2], stat_q.z);
        atomicAdd(&sq[cl * 4 + 3], stat_q.w);
    }
    __syncthreads();
    if (threadIdx.x < 64) {
        atomicAdd(&bnacc[threadIdx.x],      ss[threadIdx.x]);
        atomicAdd(&bnacc[64 + threadIdx.x], sq[threadIdx.x]);
    }
}

// ---------------- aggregation C=40: 3 groups of 10 lanes, float4 -----------
__global__ void __launch_bounds__(256, 6) k_agg40(float* __restrict__ out) {
    const float4* __restrict__ h4 = reinterpret_cast<const float4*>(g_ha);
    float4* out4 = reinterpret_cast<float4*>(out);

    const int lane = threadIdx.x & 31;
    const int warp = threadIdx.x >> 5;
    const int nwarps = gridDim.x * 8;
    const int gw = blockIdx.x * 8 + warp;
    const int g  = lane / 10;            // 0,1,2 active; lanes 30,31 idle
    const int cl = lane - g * 10;
    const bool active = (lane < 30);

    for (int node = gw; node < NN; node += nwarps) {
        float dn = g_dis[node];
        float selfn = dn * dn;
        float4 a = make_float4(0.f, 0.f, 0.f, 0.f);
        float4 b = make_float4(0.f, 0.f, 0.f, 0.f);
        if (g == 0) {
            float4 hs = h4[node * 10 + cl];
            a.x = hs.x * selfn; a.y = hs.y * selfn;
            a.z = hs.z * selfn; a.w = hs.w * selfn;
        }
        int end = g_rowptr[node + 1];
        int j   = active ? (g_rowptr[node] + g) : end;
        for (; j + 3 < end; j += 6) {
            int2 e0 = __ldg(&g_cedge[j]);
            int2 e1 = __ldg(&g_cedge[j + 3]);
            float4 v0 = __ldg(&h4[e0.x * 10 + cl]);
            float4 v1 = __ldg(&h4[e1.x * 10 + cl]);
            float w0 = __int_as_float(e0.y);
            float w1 = __int_as_float(e1.y);
            a.x = fmaf(w0, v0.x, a.x); a.y = fmaf(w0, v0.y, a.y);
            a.z = fmaf(w0, v0.z, a.z); a.w = fmaf(w0, v0.w, a.w);
            b.x = fmaf(w1, v1.x, b.x); b.y = fmaf(w1, v1.y, b.y);
            b.z = fmaf(w1, v1.z, b.z); b.w = fmaf(w1, v1.w, b.w);
        }
        if (j < end) {
            int2 e = __ldg(&g_cedge[j]);
            float4 v = __ldg(&h4[e.x * 10 + cl]);
            float w = __int_as_float(e.y);
            a.x = fmaf(w, v.x, a.x); a.y = fmaf(w, v.y, a.y);
            a.z = fmaf(w, v.z, a.z); a.w = fmaf(w, v.w, a.w);
        }
        a.x += b.x; a.y += b.y; a.z += b.z; a.w += b.w;
        __syncwarp();
        float4 t1, t2;
        t1.x = __shfl_down_sync(0xffffffffu, a.x, 10);
        t1.y = __shfl_down_sync(0xffffffffu, a.y, 10);
        t1.z = __shfl_down_sync(0xffffffffu, a.z, 10);
        t1.w = __shfl_down_sync(0xffffffffu, a.w, 10);
        t2.x = __shfl_down_sync(0xffffffffu, a.x, 20);
        t2.y = __shfl_down_sync(0xffffffffu, a.y, 20);
        t2.z = __shfl_down_sync(0xffffffffu, a.z, 20);
        t2.w = __shfl_down_sync(0xffffffffu, a.w, 20);
        if (g == 0) {
            a.x += t1.x + t2.x; a.y += t1.y + t2.y;
            a.z += t1.z + t2.z; a.w += t1.w + t2.w;
            out4[node * 10 + cl] = a;
        }
    }

    // reset BN accumulators for the next replay (already consumed)
    if (blockIdx.x == 0 && threadIdx.x < 128) {
        g_bn1[threadIdx.x] = 0.f;
        g_bn2[threadIdx.x] = 0.f;
    }
}

// ---------------- launch ----------------------------------------------------
extern "C" void kernel_launch(void* const* d_in, const int* in_sizes, int n_in,
                              void* d_out, int out_size) {
    const float* x  = (const float*)d_in[0];
    const int*   ei = (const int*)d_in[1];     // int32 (jax default)
    const float* W1 = (const float*)d_in[2];
    const float* b1 = (const float*)d_in[3];
    const float* g1 = (const float*)d_in[4];
    const float* be1= (const float*)d_in[5];
    const float* W2 = (const float*)d_in[6];
    const float* b2 = (const float*)d_in[7];
    const float* g2 = (const float*)d_in[8];
    const float* be2= (const float*)d_in[9];
    const float* W3 = (const float*)d_in[10];
    const float* b3 = (const float*)d_in[11];
    float* out = (float*)d_out;

    constexpr int SM1 = gemm_smem(128, 64);   // ~51.9 KB
    constexpr int SM2 = gemm_smem(64, 64);    // ~35.3 KB
    constexpr int SM3 = gemm_smem(64, 40);    // ~29.1 KB

    // opt into >48KB dynamic smem once (host-side attribute set; no alloc)
    static bool attr_done = false;
    if (!attr_done) {
        cudaFuncSetAttribute(k_gemm<128, 64, 1>,
                             cudaFuncAttributeMaxDynamicSharedMemorySize, SM1);
        cudaFuncSetAttribute(k_gemm<64, 64, 2>,
                             cudaFuncAttributeMaxDynamicSharedMemorySize, SM2);
        cudaFuncSetAttribute(k_gemm<64, 40, 3>,
                             cudaFuncAttributeMaxDynamicSharedMemorySize, SM3);
        attr_done = true;
    }

    // graph construction (CSR by dst) + norms
    k_count<<<592, 256>>>(ei);
    k_scan<<<NSCAN, SCAN_TILE>>>();
    k_scatter<<<592, 256>>>(ei);

    // layer 1
    k_gemm<128, 64, 1><<<592, 256, SM1>>>(x, W1, b1, nullptr, nullptr);
    k_agg64<1><<<888, 256>>>();

    // layer 2 (BN1+ReLU fused into GEMM input load)
    k_gemm<64, 64, 2><<<592, 256, SM2>>>(nullptr, W2, b2, g1, be1);
    k_agg64<2><<<888, 256>>>();

    // layer 3 (BN2+ReLU fused), C_out = 40
    k_gemm<64, 40, 3><<<592, 160, SM3>>>(nullptr, W3, b3, g2, be2);
    k_agg40<<<888, 256>>>(out);
}

// round 15
// speedup vs baseline: 1.2407x; 1.0130x over previous
#include <cuda_runtime.h>

// Problem constants
#define NN 100000
#define NE 1600000
constexpr float BN_EPS = 1e-5f;

constexpr int SCAN_TILE = 1024;
constexpr int NSCAN = (NN + SCAN_TILE - 1) / SCAN_TILE;   // 98
constexpr int NT_GEMM = (NN + 63) / 64;                   // 1563 row tiles

#define AGG_FLAG (1 << 30)
#define INC_FLAG (2 << 30)
#define VAL_MASK ((1 << 30) - 1)

// ---------------- scratch (static device globals; zero-initialized) -------
__device__ int   g_degcnt[NN];        // re-zeroed by k_scatter each replay
__device__ int   g_scanstate[NSCAN];  // re-zeroed by k_scatter each replay
__device__ float g_dis[NN];
__device__ int   g_rowptr[NN + 1];
__device__ int   g_fill[NN];
__device__ __align__(16) int2  g_cedge[NE];    // {src, float_bits(w)}
__device__ __align__(16) float g_ha[NN * 64];  // gemm outputs
__device__ __align__(16) float g_hb[NN * 64];  // agg outputs (layers 1,2)
__device__ float g_bn1[128];          // re-zeroed by k_agg40 each replay
__device__ float g_bn2[128];

// ---------------- degree count (int4-vectorized over dst half) ------------
__global__ void k_count(const int* __restrict__ ei) {
    const int4* d4 = reinterpret_cast<const int4*>(ei + NE);
    int i = blockIdx.x * blockDim.x + threadIdx.x;
    int stride = gridDim.x * blockDim.x;
    for (int e = i; e < NE / 4; e += stride) {
        int4 d = __ldg(&d4[e]);
        atomicAdd(&g_degcnt[d.x], 1);
        atomicAdd(&g_degcnt[d.y], 1);
        atomicAdd(&g_degcnt[d.z], 1);
        atomicAdd(&g_degcnt[d.w], 1);
    }
}

// ---------------- single-kernel scan, warp-parallel decoupled lookback -----
__global__ void k_scan() {
    __shared__ int sm[SCAN_TILE];
    __shared__ int s_prefix;
    const int t = threadIdx.x;
    const int b = blockIdx.x;
    const int i = b * SCAN_TILE + t;

    int v = (i < NN) ? g_degcnt[i] : 0;
    sm[t] = v;
    __syncthreads();
    #pragma unroll
    for (int off = 1; off < SCAN_TILE; off <<= 1) {
        int add = (t >= off) ? sm[t - off] : 0;
        __syncthreads();
        sm[t] += add;
        __syncthreads();
    }
    int incl = sm[t];
    int agg  = sm[SCAN_TILE - 1];

    if (t < 32) {
        if (b == 0) {
            if (t == 0) {
                atomicExch(&g_scanstate[0], INC_FLAG | agg);
                s_prefix = 0;
            }
        } else {
            if (t == 0) atomicExch(&g_scanstate[b], AGG_FLAG | agg);
            __syncwarp();
            int run = 0;
            int base = b;
            while (true) {
                int idx = base - 1 - t;
                int st = (idx >= 0) ? atomicAdd(&g_scanstate[idx], 0) : INC_FLAG;
                unsigned zero_b = __ballot_sync(0xffffffffu, st == 0);
                unsigned inc_b  = __ballot_sync(0xffffffffu, (st & INC_FLAG) != 0);
                if (inc_b != 0) {
                    int k = __ffs(inc_b) - 1;     // nearest INC lane
                    if ((zero_b & ((k == 31) ? 0xffffffffu : ((1u << (k + 1)) - 1))) == 0) {
                        int val = (t <= k) ? (st & VAL_MASK) : 0;
                        #pragma unroll
                        for (int o = 16; o > 0; o >>= 1)
                            val += __shfl_xor_sync(0xffffffffu, val, o);
                        run += val;
                        break;
                    }
                } else if (zero_b == 0) {
                    int val = st & VAL_MASK;
                    #pragma unroll
                    for (int o = 16; o > 0; o >>= 1)
                        val += __shfl_xor_sync(0xffffffffu, val, o);
                    run += val;
                    base -= 32;
                }
            }
            if (t == 0) {
                atomicExch(&g_scanstate[b], INC_FLAG | (run + agg));
                s_prefix = run;
            }
        }
    }
    __syncthreads();

    int excl = s_prefix + incl - v;
    if (i < NN) {
        g_rowptr[i] = excl;
        g_fill[i]   = excl;
        g_dis[i]    = rsqrtf((float)(v + 1));
    }
    if (i == 0) g_rowptr[NN] = NE;
}

// ---------------- CSR scatter (int4 loads) + state resets ------------------
__global__ void k_scatter(const int* __restrict__ ei) {
    const int4* s4 = reinterpret_cast<const int4*>(ei);
    const int4* d4 = reinterpret_cast<const int4*>(ei + NE);
    int i = blockIdx.x * blockDim.x + threadIdx.x;
    int stride = gridDim.x * blockDim.x;
    for (int e = i; e < NE / 4; e += stride) {
        int4 s = __ldg(&s4[e]);
        int4 d = __ldg(&d4[e]);
        {
            float w = g_dis[s.x] * g_dis[d.x];
            g_cedge[atomicAdd(&g_fill[d.x], 1)] = make_int2(s.x, __float_as_int(w));
        }
        {
            float w = g_dis[s.y] * g_dis[d.y];
            g_cedge[atomicAdd(&g_fill[d.y], 1)] = make_int2(s.y, __float_as_int(w));
        }
        {
            float w = g_dis[s.z] * g_dis[d.z];
            g_cedge[atomicAdd(&g_fill[d.z], 1)] = make_int2(s.z, __float_as_int(w));
        }
        {
            float w = g_dis[s.w] * g_dis[d.w];
            g_cedge[atomicAdd(&g_fill[d.w], 1)] = make_int2(s.w, __float_as_int(w));
        }
    }
    for (int n = i; n < NN; n += stride) g_degcnt[n] = 0;
    if (i < NSCAN) g_scanstate[i] = 0;
}

// ---------------- f32x2 helpers --------------------------------------------
__device__ __forceinline__ void ffma2(unsigned long long& d,
                                      unsigned long long a,
                                      unsigned long long b) {
    asm("fma.rn.f32x2 %0, %1, %2, %0;" : "+l"(d) : "l"(a), "l"(b));
}
__device__ __forceinline__ unsigned long long dup2(float x) {
    unsigned long long r;
    asm("mov.b64 %0, {%1, %1};" : "=l"(r) : "r"(__float_as_int(x)));
    return r;
}

// ---------------- persistent GEMM, reg-staged prefetch pipeline ------------
// Per chunk: LDG next chunk -> REGISTERS (no wait), compute current chunk
// (covers the 577-cyc DRAM latency), then regs -> smem, one barrier.
// DYNAMIC shared memory. Layout (floats):
//   Ws[K*COUT] | Bs[COUT] | sSc[64] | sSh[64] | Xs0[RB*XSTR] | Xs1[RB*XSTR]
template <int K, int COUT, int LAYER>
__global__ void __launch_bounds__((COUT / 4) * 16, 4) k_gemm(
        const float* __restrict__ Xext,
        const float* __restrict__ W,
        const float* __restrict__ Bb,
        const float* __restrict__ gamma,
        const float* __restrict__ beta) {
    constexpr int TM = 4, TN = 4;
    constexpr int COLT = COUT / TN;       // 16 or 10
    constexpr int ROWT = 16;
    constexpr int RB   = ROWT * TM;       // 64 rows per tile
    constexpr int KC   = 32;
    constexpr int NCH  = K / KC;          // chunks per tile (4 or 2)
    constexpr int NTH  = COLT * ROWT;
    constexpr int XSTR = KC + 4;          // 36: 16B-aligned, conflict-free
    constexpr int NV   = RB * (KC / 4);   // 512 float4 per chunk
    constexpr int NLD  = (NV + NTH - 1) / NTH;   // 2 (or 4 for 160 thr)

    extern __shared__ __align__(16) float smem_dyn[];
    float* Ws  = smem_dyn;                       // K*COUT
    float* Bs  = Ws + K * COUT;                  // COUT
    float* sSc = Bs + COUT;                      // 64
    float* sSh = sSc + 64;                       // 64
    float* Xs0 = sSh + 64;                       // RB*XSTR
    float* Xs1 = Xs0 + RB * XSTR;                // RB*XSTR

    const float* Xp = (LAYER == 1) ? Xext : g_hb;
    float* out = g_ha;

    const int tid  = threadIdx.x;
    const int colt = tid % COLT;
    const int rowt = tid / COLT;

    for (int idx = tid; idx < K * COUT; idx += NTH) Ws[idx] = W[idx];
    for (int idx = tid; idx < COUT; idx += NTH)     Bs[idx] = Bb[idx];
    if (LAYER != 1) {
        if (tid < K) {   // K == 64 for layers 2,3
            const float* acc = (LAYER == 2) ? g_bn1 : g_bn2;
            float inv_n = 1.0f / (float)NN;
            float mu  = acc[tid] * inv_n;
            float var = acc[64 + tid] * inv_n - mu * mu;
            float inv = rsqrtf(var + BN_EPS);
            float s = gamma[tid] * inv;
            sSc[tid] = s;
            sSh[tid] = fmaf(-mu, s, beta[tid]);
        }
    }
    __syncthreads();   // Ws/Bs/sSc/sSh visible before any stage/compute

    // issue LDGs for one chunk into registers (no smem, no waiting readers)
    auto stage_load = [&](int tile, int chunk, float4* v) {
        const int rowBase = tile * RB;
        const int k0 = chunk * KC;
        #pragma unroll
        for (int L = 0; L < NLD; L++) {
            int idx = tid + L * NTH;
            float4 t = make_float4(0.f, 0.f, 0.f, 0.f);
            if (idx < NV) {
                int r  = idx >> 3;
                int c4 = idx & 7;
                int gr = rowBase + r;
                if (gr < NN)
                    t = *reinterpret_cast<const float4*>(
                        &Xp[(long)gr * K + k0 + c4 * 4]);
            }
            v[L] = t;
        }
    };

    // write staged registers to smem (BN+ReLU applied here)
    auto stage_store = [&](const float4* v, int chunk, float* xs) {
        const int k0 = chunk * KC;
        #pragma unroll
        for (int L = 0; L < NLD; L++) {
            int idx = tid + L * NTH;
            if (idx < NV) {
                int r  = idx >> 3;
                int c4 = idx & 7;
                float4 t = v[L];
                if (LAYER != 1) {
                    int kk = k0 + c4 * 4;
                    t.x = fmaxf(fmaf(t.x, sSc[kk    ], sSh[kk    ]), 0.f);
                    t.y = fmaxf(fmaf(t.y, sSc[kk + 1], sSh[kk + 1]), 0.f);
                    t.z = fmaxf(fmaf(t.z, sSc[kk + 2], sSh[kk + 2]), 0.f);
                    t.w = fmaxf(fmaf(t.w, sSc[kk + 3], sSh[kk + 3]), 0.f);
                }
                *reinterpret_cast<float4*>(&xs[r * XSTR + c4 * 4]) = t;
            }
        }
    };

    int tile = blockIdx.x;
    int buf = 0;
    if (tile < NT_GEMM) {
        float4 v0[NLD];
        stage_load(tile, 0, v0);
        stage_store(v0, 0, Xs0);
    }
    __syncthreads();

    for (; tile < NT_GEMM; tile += gridDim.x) {
        const int rowBase = tile * RB;

        unsigned long long acc[TM][2];
        #pragma unroll
        for (int i = 0; i < TM; i++) { acc[i][0] = 0ull; acc[i][1] = 0ull; }

        #pragma unroll
        for (int chunk = 0; chunk < NCH; chunk++) {
            int ntile  = (chunk + 1 < NCH) ? tile : tile + gridDim.x;
            int nchunk = (chunk + 1 < NCH) ? chunk + 1 : 0;
            bool have  = (ntile < NT_GEMM);

            // 1) issue next chunk's LDGs into registers (latency overlapped)
            float4 v[NLD];
            if (have) stage_load(ntile, nchunk, v);

            // 2) compute current chunk from smem
            const int k0 = chunk * KC;
            const float* xs = buf ? Xs1 : Xs0;
            const float* xbase = &xs[rowt * TM * XSTR];

            #pragma unroll
            for (int k4 = 0; k4 < KC / 4; k4++) {
                ulonglong2 wv[4];
                #pragma unroll
                for (int kk = 0; kk < 4; kk++)
                    wv[kk] = *reinterpret_cast<const ulonglong2*>(
                        &Ws[(k0 + k4 * 4 + kk) * COUT + colt * TN]);
                #pragma unroll
                for (int i = 0; i < TM; i++) {
                    float4 xr = *reinterpret_cast<const float4*>(
                        &xbase[i * XSTR + k4 * 4]);
                    unsigned long long xx;
                    xx = dup2(xr.x);
                    ffma2(acc[i][0], xx, wv[0].x); ffma2(acc[i][1], xx, wv[0].y);
                    xx = dup2(xr.y);
                    ffma2(acc[i][0], xx, wv[1].x); ffma2(acc[i][1], xx, wv[1].y);
                    xx = dup2(xr.z);
                    ffma2(acc[i][0], xx, wv[2].x); ffma2(acc[i][1], xx, wv[2].y);
                    xx = dup2(xr.w);
                    ffma2(acc[i][0], xx, wv[3].x); ffma2(acc[i][1], xx, wv[3].y);
                }
            }

            // 3) drain staged regs into the other buffer; single barrier
            if (have) stage_store(v, nchunk, buf ? Xs0 : Xs1);
            __syncthreads();
            buf ^= 1;
        }

        float4 b4 = *reinterpret_cast<const float4*>(&Bs[colt * TN]);
        #pragma unroll
        for (int i = 0; i < TM; i++) {
            int gr = rowBase + rowt * TM + i;
            if (gr < NN) {
                float2 p01 = *reinterpret_cast<float2*>(&acc[i][0]);
                float2 p23 = *reinterpret_cast<float2*>(&acc[i][1]);
                float4 o;
                o.x = p01.x + b4.x;
                o.y = p01.y + b4.y;
                o.z = p23.x + b4.z;
                o.w = p23.y + b4.w;
                *reinterpret_cast<float4*>(&out[(long)gr * COUT + colt * TN]) = o;
            }
        }
    }
}

// dynamic smem byte counts per instantiation
constexpr int gemm_smem(int K, int COUT) {
    return (K * COUT + COUT + 128 + 2 * 64 * 36) * (int)sizeof(float);
}

// ---------------- aggregation C=64: half-warp per edge, float4 lanes -------
template <int LAYER>
__global__ void __launch_bounds__(256, 6) k_agg64() {
    const float4* __restrict__ h4 = reinterpret_cast<const float4*>(g_ha);
    float4* out4 = reinterpret_cast<float4*>(g_hb);
    float* bnacc = (LAYER == 1) ? g_bn1 : g_bn2;

    const int lane = threadIdx.x & 31;
    const int warp = threadIdx.x >> 5;
    const int nwarps = gridDim.x * 8;
    const int gw = blockIdx.x * 8 + warp;
    const int g  = lane >> 4;        // edge-parity group (0/1)
    const int cl = lane & 15;        // float4 channel quad

    float4 stat_s = make_float4(0.f, 0.f, 0.f, 0.f);
    float4 stat_q = make_float4(0.f, 0.f, 0.f, 0.f);

    for (int node = gw; node < NN; node += nwarps) {
        float dn = g_dis[node];
        float selfn = dn * dn;
        float4 a = make_float4(0.f, 0.f, 0.f, 0.f);
        float4 b = make_float4(0.f, 0.f, 0.f, 0.f);
        if (g == 0) {
            float4 hs = h4[node * 16 + cl];
            a.x = hs.x * selfn; a.y = hs.y * selfn;
            a.z = hs.z * selfn; a.w = hs.w * selfn;
        }
        int j   = g_rowptr[node] + g;
        int end = g_rowptr[node + 1];
        for (; j + 2 < end; j += 4) {
            int2 e0 = __ldg(&g_cedge[j]);
            int2 e1 = __ldg(&g_cedge[j + 2]);
            float4 v0 = __ldg(&h4[e0.x * 16 + cl]);
            float4 v1 = __ldg(&h4[e1.x * 16 + cl]);
            float w0 = __int_as_float(e0.y);
            float w1 = __int_as_float(e1.y);
            a.x = fmaf(w0, v0.x, a.x); a.y = fmaf(w0, v0.y, a.y);
            a.z = fmaf(w0, v0.z, a.z); a.w = fmaf(w0, v0.w, a.w);
            b.x = fmaf(w1, v1.x, b.x); b.y = fmaf(w1, v1.y, b.y);
            b.z = fmaf(w1, v1.z, b.z); b.w = fmaf(w1, v1.w, b.w);
        }
        if (j < end) {
            int2 e = __ldg(&g_cedge[j]);
            float4 v = __ldg(&h4[e.x * 16 + cl]);
            float w = __int_as_float(e.y);
            a.x = fmaf(w, v.x, a.x); a.y = fmaf(w, v.y, a.y);
            a.z = fmaf(w, v.z, a.z); a.w = fmaf(w, v.w, a.w);
        }
        a.x += b.x; a.y += b.y; a.z += b.z; a.w += b.w;
        __syncwarp();
        a.x += __shfl_xor_sync(0xffffffffu, a.x, 16);
        a.y += __shfl_xor_sync(0xffffffffu, a.y, 16);
        a.z += __shfl_xor_sync(0xffffffffu, a.z, 16);
        a.w += __shfl_xor_sync(0xffffffffu, a.w, 16);
        if (g == 0) {
            out4[node * 16 + cl] = a;
            stat_s.x += a.x; stat_s.y += a.y; stat_s.z += a.z; stat_s.w += a.w;
            stat_q.x += a.x * a.x; stat_q.y += a.y * a.y;
            stat_q.z += a.z * a.z; stat_q.w += a.w * a.w;
        }
    }

    __shared__ float ss[64], sq[64];
    if (threadIdx.x < 64) { ss[threadIdx.x] = 0.f; sq[threadIdx.x] = 0.f; }
    __syncthreads();
    if (g == 0) {
        atomicAdd(&ss[cl * 4    ], stat_s.x);
        atomicAdd(&ss[cl * 4 + 1], stat_s.y);
        atomicAdd(&ss[cl * 4 + 2], stat_s.z);
        atomicAdd(&ss[cl * 4 + 3], stat_s.w);
        atomicAdd(&sq[cl * 4    ], stat_q.x);
        atomicAdd(&sq[cl * 4 + 1], stat_q.y);
        atomicAdd(&sq[cl * 4 + 2], stat_q.z);
        atomicAdd(&sq[cl * 4 + 3], stat_q.w);
    }
    __syncthreads();
    if (threadIdx.x < 64) {
        atomicAdd(&bnacc[threadIdx.x],      ss[threadIdx.x]);
        atomicAdd(&bnacc[64 + threadIdx.x], sq[threadIdx.x]);
    }
}

// ---------------- aggregation C=40: 3 groups of 10 lanes, float4 -----------
__global__ void __launch_bounds__(256, 6) k_agg40(float* __restrict__ out) {
    const float4* __restrict__ h4 = reinterpret_cast<const float4*>(g_ha);
    float4* out4 = reinterpret_cast<float4*>(out);

    const int lane = threadIdx.x & 31;
    const int warp = threadIdx.x >> 5;
    const int nwarps = gridDim.x * 8;
    const int gw = blockIdx.x * 8 + warp;
    const int g  = lane / 10;            // 0,1,2 active; lanes 30,31 idle
    const int cl = lane - g * 10;
    const bool active = (lane < 30);

    for (int node = gw; node < NN; node += nwarps) {
        float dn = g_dis[node];
        float selfn = dn * dn;
        float4 a = make_float4(0.f, 0.f, 0.f, 0.f);
        float4 b = make_float4(0.f, 0.f, 0.f, 0.f);
        if (g == 0) {
            float4 hs = h4[node * 10 + cl];
            a.x = hs.x * selfn; a.y = hs.y * selfn;
            a.z = hs.z * selfn; a.w = hs.w * selfn;
        }
        int end = g_rowptr[node + 1];
        int j   = active ? (g_rowptr[node] + g) : end;
        for (; j + 3 < end; j += 6) {
            int2 e0 = __ldg(&g_cedge[j]);
            int2 e1 = __ldg(&g_cedge[j + 3]);
            float4 v0 = __ldg(&h4[e0.x * 10 + cl]);
            float4 v1 = __ldg(&h4[e1.x * 10 + cl]);
            float w0 = __int_as_float(e0.y);
            float w1 = __int_as_float(e1.y);
            a.x = fmaf(w0, v0.x, a.x); a.y = fmaf(w0, v0.y, a.y);
            a.z = fmaf(w0, v0.z, a.z); a.w = fmaf(w0, v0.w, a.w);
            b.x = fmaf(w1, v1.x, b.x); b.y = fmaf(w1, v1.y, b.y);
            b.z = fmaf(w1, v1.z, b.z); b.w = fmaf(w1, v1.w, b.w);
        }
        if (j < end) {
            int2 e = __ldg(&g_cedge[j]);
            float4 v = __ldg(&h4[e.x * 10 + cl]);
            float w = __int_as_float(e.y);
            a.x = fmaf(w, v.x, a.x); a.y = fmaf(w, v.y, a.y);
            a.z = fmaf(w, v.z, a.z); a.w = fmaf(w, v.w, a.w);
        }
        a.x += b.x; a.y += b.y; a.z += b.z; a.w += b.w;
        __syncwarp();
        float4 t1, t2;
        t1.x = __shfl_down_sync(0xffffffffu, a.x, 10);
        t1.y = __shfl_down_sync(0xffffffffu, a.y, 10);
        t1.z = __shfl_down_sync(0xffffffffu, a.z, 10);
        t1.w = __shfl_down_sync(0xffffffffu, a.w, 10);
        t2.x = __shfl_down_sync(0xffffffffu, a.x, 20);
        t2.y = __shfl_down_sync(0xffffffffu, a.y, 20);
        t2.z = __shfl_down_sync(0xffffffffu, a.z, 20);
        t2.w = __shfl_down_sync(0xffffffffu, a.w, 20);
        if (g == 0) {
            a.x += t1.x + t2.x; a.y += t1.y + t2.y;
            a.z += t1.z + t2.z; a.w += t1.w + t2.w;
            out4[node * 10 + cl] = a;
        }
    }

    // reset BN accumulators for the next replay (already consumed)
    if (blockIdx.x == 0 && threadIdx.x < 128) {
        g_bn1[threadIdx.x] = 0.f;
        g_bn2[threadIdx.x] = 0.f;
    }
}

// ---------------- launch ----------------------------------------------------
extern "C" void kernel_launch(void* const* d_in, const int* in_sizes, int n_in,
                              void* d_out, int out_size) {
    const float* x  = (const float*)d_in[0];
    const int*   ei = (const int*)d_in[1];     // int32 (jax default)
    const float* W1 = (const float*)d_in[2];
    const float* b1 = (const float*)d_in[3];
    const float* g1 = (const float*)d_in[4];
    const float* be1= (const float*)d_in[5];
    const float* W2 = (const float*)d_in[6];
    const float* b2 = (const float*)d_in[7];
    const float* g2 = (const float*)d_in[8];
    const float* be2= (const float*)d_in[9];
    const float* W3 = (const float*)d_in[10];
    const float* b3 = (const float*)d_in[11];
    float* out = (float*)d_out;

    constexpr int SM1 = gemm_smem(128, 64);   // ~51.9 KB
    constexpr int SM2 = gemm_smem(64, 64);    // ~35.3 KB
    constexpr int SM3 = gemm_smem(64, 40);    // ~29.1 KB

    // opt into >48KB dynamic smem once (host-side attribute set; no alloc)
    static bool attr_done = false;
    if (!attr_done) {
        cudaFuncSetAttribute(k_gemm<128, 64, 1>,
                             cudaFuncAttributeMaxDynamicSharedMemorySize, SM1);
        cudaFuncSetAttribute(k_gemm<64, 64, 2>,
                             cudaFuncAttributeMaxDynamicSharedMemorySize, SM2);
        cudaFuncSetAttribute(k_gemm<64, 40, 3>,
                             cudaFuncAttributeMaxDynamicSharedMemorySize, SM3);
        attr_done = true;
    }

    // graph construction (CSR by dst) + norms
    k_count<<<592, 256>>>(ei);
    k_scan<<<NSCAN, SCAN_TILE>>>();
    k_scatter<<<592, 256>>>(ei);

    // layer 1
    k_gemm<128, 64, 1><<<592, 256, SM1>>>(x, W1, b1, nullptr, nullptr);
    k_agg64<1><<<888, 256>>>();

    // layer 2 (BN1+ReLU fused into GEMM input load)
    k_gemm<64, 64, 2><<<592, 256, SM2>>>(nullptr, W2, b2, g1, be1);
    k_agg64<2><<<888, 256>>>();

    // layer 3 (BN2+ReLU fused), C_out = 40
    k_gemm<64, 40, 3><<<592, 160, SM3>>>(nullptr, W3, b3, g2, be2);
    k_agg40<<<888, 256>>>(out);
}